// round 3
// baseline (speedup 1.0000x reference)
#include <cuda_runtime.h>
#include <math.h>

#define THREADS 64
#define NJ 12

// Output layout (flattened tuple, float32):
//   outs : [B][3][4][4]  at offset 0            (B*48)
//   revls: [B][12][6]    at offset B*48         (B*72)
//   prils: [B][12][6]    at offset B*120        (B*72)

__global__ __launch_bounds__(THREADS) void poe_kernel(
    const float* __restrict__ q,
    const float* __restrict__ rev,
    const float* __restrict__ pri,
    const float* __restrict__ pos,
    const float* __restrict__ ori,
    float* __restrict__ out, int B)
{
    // per-twist constants: stride 24 floats per twist, 24 twists
    __shared__ float s_tw[24 * 24];
    __shared__ float s_tool[3 * 12];
    __shared__ float s_q[THREADS * 25];   // padded stride 25 (conflict-free)
    __shared__ float s_rev[THREADS * 73]; // padded stride 73 (conflict-free)
    __shared__ float s_pri[THREADS * 73];

    const int tid = threadIdx.x;
    const int b0 = blockIdx.x * THREADS;

    // ---------------- setup: twist constants ----------------
    if (tid < 24) {
        int j = tid >> 1;
        const float* xi = (tid & 1) ? (pri + j * 6) : (rev + j * 6);
        float wx = xi[0], wy = xi[1], wz = xi[2];
        float vx = xi[3], vy = xi[4], vz = xi[5];
        float ww = wx * wx + wy * wy + wz * wz;
        float a2 = ww + 1e-12f;
        float a = sqrtf(a2);
        float inva = 1.0f / a;
        float inva2 = 1.0f / a2;
        float* t = s_tw + tid * 24;
        t[0] = wx; t[1] = wy; t[2] = wz;
        t[3] = vx; t[4] = vy; t[5] = vz;
        t[6] = a;
        // hat(w)^2 = w w^T - (w.w) I   (exact ww, no eps — matches wh@wh)
        float W2xx = wx * wx - ww, W2xy = wx * wy, W2xz = wx * wz;
        float W2yy = wy * wy - ww, W2yz = wy * wz, W2zz = wz * wz - ww;
        t[7] = W2xx; t[8] = W2xy; t[9] = W2xz;
        t[10] = W2yy; t[11] = W2yz; t[12] = W2zz;
        // w x v
        t[13] = wy * vz - wz * vy;
        t[14] = wz * vx - wx * vz;
        t[15] = wx * vy - wy * vx;
        // hat(w)^2 @ v
        t[16] = W2xx * vx + W2xy * vy + W2xz * vz;
        t[17] = W2xy * vx + W2yy * vy + W2yz * vz;
        t[18] = W2xz * vx + W2yz * vy + W2zz * vz;
        t[19] = inva;          // 1/a
        t[20] = inva2;         // 1/a^2
        t[21] = inva * inva2;  // 1/a^3
    } else if (tid < 27) {
        // tool matrices for branch joints 3, 7, 11
        int k = tid - 24;
        int idx = 4 * k + 3;
        float rr = ori[idx * 3 + 0], pp = ori[idx * 3 + 1], yy = ori[idx * 3 + 2];
        float cr, sr, cp, sp, cy, sy;
        sincosf(rr, &sr, &cr);
        sincosf(pp, &sp, &cp);
        sincosf(yy, &sy, &cy);
        float* tl = s_tool + k * 12;
        tl[0] = cy * cp; tl[1] = cy * sp * sr - sy * cr; tl[2] = cy * sp * cr + sy * sr;
        tl[3] = sy * cp; tl[4] = sy * sp * sr + cy * cr; tl[5] = sy * sp * cr - cy * sr;
        tl[6] = -sp;     tl[7] = cp * sr;                tl[8] = cp * cr;
        tl[9] = pos[idx * 3 + 0]; tl[10] = pos[idx * 3 + 1]; tl[11] = pos[idx * 3 + 2];
    }

    // ---------------- stage q into shared (coalesced) ----------------
    {
        int nel = B - b0; if (nel > THREADS) nel = THREADS;
        if (nel == THREADS) {
            const float4* gq = (const float4*)(q + (long long)b0 * 24);
            #pragma unroll
            for (int i4 = tid; i4 < THREADS * 24 / 4; i4 += THREADS) {
                float4 v = gq[i4];
                int i = i4 * 4;
                int e = i / 24, r = i - e * 24;
                float* d = s_q + e * 25 + r;
                d[0] = v.x; d[1] = v.y; d[2] = v.z; d[3] = v.w;
            }
        } else {
            for (int i = tid; i < nel * 24; i += THREADS) {
                int e = i / 24, r = i - e * 24;
                s_q[e * 25 + r] = q[(long long)b0 * 24 + i];
            }
        }
    }
    __syncthreads();

    // ---------------- main per-element loop ----------------
    const long long b = (long long)b0 + tid;
    const long long Boff = (long long)B;

    if (b < B) {
        // affine T = [R | p], starts identity
        float R00 = 1.f, R01 = 0.f, R02 = 0.f;
        float R10 = 0.f, R11 = 1.f, R12 = 0.f;
        float R20 = 0.f, R21 = 0.f, R22 = 1.f;
        float px = 0.f, py = 0.f, pz = 0.f;

        float* srevBase = s_rev + tid * 73;
        float* spriBase = s_pri + tid * 73;
        const float* sqBase = s_q + tid * 25;

        #pragma unroll 4
        for (int j = 0; j < NJ; j++) {
            #pragma unroll
            for (int half = 0; half < 2; half++) {
                const float* t = s_tw + (2 * j + half) * 24;
                float wx = t[0], wy = t[1], wz = t[2];
                float vx = t[3], vy = t[4], vz = t[5];

                // ---- adj_inv(T) applied to xi -> (wp, vp) ----
                float wpx = R00 * wx + R10 * wy + R20 * wz;
                float wpy = R01 * wx + R11 * wy + R21 * wz;
                float wpz = R02 * wx + R12 * wy + R22 * wz;
                float ux = vx - (py * wz - pz * wy);
                float uy = vy - (pz * wx - px * wz);
                float uz = vz - (px * wy - py * wx);
                float vpx = R00 * ux + R10 * uy + R20 * uz;
                float vpy = R01 * ux + R11 * uy + R21 * uz;
                float vpz = R02 * ux + R12 * uy + R22 * uz;
                float* sdst = (half ? spriBase : srevBase) + j * 6;
                sdst[0] = wpx; sdst[1] = wpy; sdst[2] = wpz;
                sdst[3] = vpx; sdst[4] = vpy; sdst[5] = vpz;

                // ---- E = exp(xi * th) ----
                float th = sqBase[2 * j + half];
                float a = t[6];
                float ang = a * th;
                float s, c;
                sincosf(ang, &s, &c);
                float k1 = s * t[19];
                float k2 = (1.0f - c) * t[20];
                float k3 = (ang - s) * t[21];
                float E00 = 1.f + k2 * t[7];
                float E01 = -k1 * wz + k2 * t[8];
                float E02 =  k1 * wy + k2 * t[9];
                float E10 =  k1 * wz + k2 * t[8];
                float E11 = 1.f + k2 * t[10];
                float E12 = -k1 * wx + k2 * t[11];
                float E20 = -k1 * wy + k2 * t[9];
                float E21 =  k1 * wx + k2 * t[11];
                float E22 = 1.f + k2 * t[12];
                float ex = th * vx + k2 * t[13] + k3 * t[16];
                float ey = th * vy + k2 * t[14] + k3 * t[17];
                float ez = th * vz + k2 * t[15] + k3 * t[18];

                // ---- T = T * E (use old R for translation) ----
                float npx = px + R00 * ex + R01 * ey + R02 * ez;
                float npy = py + R10 * ex + R11 * ey + R12 * ez;
                float npz = pz + R20 * ex + R21 * ey + R22 * ez;
                float n00 = R00 * E00 + R01 * E10 + R02 * E20;
                float n01 = R00 * E01 + R01 * E11 + R02 * E21;
                float n02 = R00 * E02 + R01 * E12 + R02 * E22;
                float n10 = R10 * E00 + R11 * E10 + R12 * E20;
                float n11 = R10 * E01 + R11 * E11 + R12 * E21;
                float n12 = R10 * E02 + R11 * E12 + R12 * E22;
                float n20 = R20 * E00 + R21 * E10 + R22 * E20;
                float n21 = R20 * E01 + R21 * E11 + R22 * E21;
                float n22 = R20 * E02 + R21 * E12 + R22 * E22;
                R00 = n00; R01 = n01; R02 = n02;
                R10 = n10; R11 = n11; R12 = n12;
                R20 = n20; R21 = n21; R22 = n22;
                px = npx; py = npy; pz = npz;
            }

            // branch outputs at j = 3, 7, 11
            if ((j & 3) == 3) {
                int k = j >> 2;
                const float* tl = s_tool + k * 12;
                float O00 = R00 * tl[0] + R01 * tl[3] + R02 * tl[6];
                float O01 = R00 * tl[1] + R01 * tl[4] + R02 * tl[7];
                float O02 = R00 * tl[2] + R01 * tl[5] + R02 * tl[8];
                float O10 = R10 * tl[0] + R11 * tl[3] + R12 * tl[6];
                float O11 = R10 * tl[1] + R11 * tl[4] + R12 * tl[7];
                float O12 = R10 * tl[2] + R11 * tl[5] + R12 * tl[8];
                float O20 = R20 * tl[0] + R21 * tl[3] + R22 * tl[6];
                float O21 = R20 * tl[1] + R21 * tl[4] + R22 * tl[7];
                float O22 = R20 * tl[2] + R21 * tl[5] + R22 * tl[8];
                float pox = R00 * tl[9] + R01 * tl[10] + R02 * tl[11] + px;
                float poy = R10 * tl[9] + R11 * tl[10] + R12 * tl[11] + py;
                float poz = R20 * tl[9] + R21 * tl[10] + R22 * tl[11] + pz;
                float4* dst = (float4*)(out + b * 48 + k * 16);
                dst[0] = make_float4(O00, O01, O02, pox);
                dst[1] = make_float4(O10, O11, O12, poy);
                dst[2] = make_float4(O20, O21, O22, poz);
                dst[3] = make_float4(0.f, 0.f, 0.f, 1.f);
            }
        }
    }
    __syncthreads();

    // ---------------- coalesced flush of revls / prils ----------------
    {
        int nel = B - b0; if (nel > THREADS) nel = THREADS;
        float* revg = out + Boff * 48 + (long long)b0 * 72;
        float* prig = out + Boff * 120 + (long long)b0 * 72;
        if (nel == THREADS) {
            float4* r4 = (float4*)revg;
            float4* p4 = (float4*)prig;
            #pragma unroll 2
            for (int i4 = tid; i4 < THREADS * 72 / 4; i4 += THREADS) {
                int i = i4 * 4;
                int e = i / 72, r = i - e * 72;
                const float* sa = s_rev + e * 73 + r;
                r4[i4] = make_float4(sa[0], sa[1], sa[2], sa[3]);
                const float* sb = s_pri + e * 73 + r;
                p4[i4] = make_float4(sb[0], sb[1], sb[2], sb[3]);
            }
        } else {
            for (int i = tid; i < nel * 72; i += THREADS) {
                int e = i / 72, r = i - e * 72;
                revg[i] = s_rev[e * 73 + r];
                prig[i] = s_pri[e * 73 + r];
            }
        }
    }
}

extern "C" void kernel_launch(void* const* d_in, const int* in_sizes, int n_in,
                              void* d_out, int out_size)
{
    const float* q   = (const float*)d_in[0];
    const float* rev = (const float*)d_in[1];
    const float* pri = (const float*)d_in[2];
    const float* pos = (const float*)d_in[3];
    const float* ori = (const float*)d_in[4];
    float* out = (float*)d_out;
    int B = in_sizes[0] / 24;
    int grid = (B + THREADS - 1) / THREADS;
    poe_kernel<<<grid, THREADS>>>(q, rev, pri, pos, ori, out, B);
}